// round 13
// baseline (speedup 1.0000x reference)
#include <cuda_runtime.h>
#include <math.h>

// Problem constants
#define B_SZ 256
#define T_SZ 96
#define F_DIM 368
#define D_MODEL 368
#define G3 1104          // 3*D_MODEL
#define NCLS 29
#define NOUT 31          // 2 coarse + 29 fine
#define M_ROWS 24576     // B*T

// -------- device scratch --------
__device__ float g_xprojT[(size_t)T_SZ * D_MODEL * 3 * B_SZ];  // [t][u][g][b]
__device__ float g_h[(size_t)T_SZ * D_MODEL * B_SZ];           // [t][d][b]
__device__ float g_logitsT[(size_t)T_SZ * B_SZ * NOUT];        // [t][b][o]
__device__ unsigned g_bars[8];                                 // per-batch-group barriers

// -------- packed f32x2 helpers (Blackwell FFMA2) --------
__device__ __forceinline__ unsigned long long dup_f32(float f) {
    unsigned long long r;
    asm("mov.b64 %0, {%1, %1};" : "=l"(r) : "r"(__float_as_uint(f)));
    return r;
}
__device__ __forceinline__ void fma2(unsigned long long& d,
                                     unsigned long long a, unsigned long long b) {
    asm("fma.rn.f32x2 %0, %1, %2, %0;" : "+l"(d) : "l"(a), "l"(b));
}
__device__ __forceinline__ float2 unpack2(unsigned long long v) {
    unsigned lo, hi;
    asm("mov.b64 {%0, %1}, %2;" : "=r"(lo), "=r"(hi) : "l"(v));
    return make_float2(__uint_as_float(lo), __uint_as_float(hi));
}
__device__ __forceinline__ float fast_sigmoid(float x) {
    return __fdividef(1.f, 1.f + expf(-x));
}
__device__ __forceinline__ float fast_tanh(float x) {
    return __fdividef(2.f, 1.f + expf(-2.f * x)) - 1.f;
}

// -------- cp.async helpers --------
__device__ __forceinline__ void cp16(void* smem_dst, const void* gsrc) {
    unsigned d = (unsigned)__cvta_generic_to_shared(smem_dst);
    asm volatile("cp.async.cg.shared.global [%0], [%1], 16;\n" :: "r"(d), "l"(gsrc));
}
__device__ __forceinline__ void cp_commit() {
    asm volatile("cp.async.commit_group;\n");
}
template <int N>
__device__ __forceinline__ void cp_wait() {
    asm volatile("cp.async.wait_group %0;\n" :: "n"(N));
}

// ============================================================
// init kernel: reset barriers (runs each graph replay)
// ============================================================
__global__ void init_bar_kernel() {
    for (int i = 0; i < 8; i++) g_bars[i] = 0u;
}

// ============================================================
// Kernel 1: xproj direct into [t][u][g][b] layout.
// grid (18 n-tiles, 2 b-tiles, 96 t), 256 threads, BK=16, tile 8b x 4n
// ============================================================
__global__ void xproj_kernel(const float* __restrict__ A,
                             const float* __restrict__ W,
                             const float* __restrict__ bi)
{
    __shared__ float As[16][128];
    __shared__ float Bs[16][64];

    const int t  = blockIdx.z;
    const int b0 = blockIdx.y * 128;
    const int n0 = blockIdx.x * 64;
    const int tid = threadIdx.x;
    const int tx = tid & 15;        // 4 n each
    const int ty = tid >> 4;        // 8 b each

    unsigned long long accp[8][2];
#pragma unroll
    for (int i = 0; i < 8; i++) { accp[i][0] = 0ull; accp[i][1] = 0ull; }

    for (int k0 = 0; k0 < F_DIM; k0 += 16) {
#pragma unroll
        for (int l = 0; l < 2; l++) {
            int idx = tid + l * 256;
            int row = idx >> 2, kq = idx & 3;   // row = batch lane
            float4 v = *(const float4*)(A + ((size_t)(b0 + row) * T_SZ + t) * F_DIM + k0 + kq * 4);
            As[kq * 4 + 0][row] = v.x;
            As[kq * 4 + 1][row] = v.y;
            As[kq * 4 + 2][row] = v.z;
            As[kq * 4 + 3][row] = v.w;
        }
        {
            int row = tid >> 2, kq = tid & 3;
            int n = n0 + row;
            float4 v = make_float4(0.f, 0.f, 0.f, 0.f);
            if (n < G3)
                v = *(const float4*)(W + (size_t)n * F_DIM + k0 + kq * 4);
            Bs[kq * 4 + 0][row] = v.x;
            Bs[kq * 4 + 1][row] = v.y;
            Bs[kq * 4 + 2][row] = v.z;
            Bs[kq * 4 + 3][row] = v.w;
        }
        __syncthreads();
#pragma unroll
        for (int k = 0; k < 16; k++) {
            ulonglong2 bq = *(const ulonglong2*)&Bs[k][tx * 4];
#pragma unroll
            for (int i = 0; i < 8; i++) {
                unsigned long long ap = dup_f32(As[k][ty * 8 + i]);
                fma2(accp[i][0], ap, bq.x);
                fma2(accp[i][1], ap, bq.y);
            }
        }
        __syncthreads();
    }

    // write transposed: for each n, 8 consecutive batches
#pragma unroll
    for (int j = 0; j < 4; j++) {
        int n = n0 + tx * 4 + j;
        if (n < G3) {
            int g = n / D_MODEL, u = n - g * D_MODEL;
            float bv = bi[n];
            float col[8];
#pragma unroll
            for (int i = 0; i < 8; i++) {
                float2 p = unpack2(accp[i][j >> 1]);
                col[i] = ((j & 1) ? p.y : p.x) + bv;
            }
            float* dst = g_xprojT + (((size_t)t * D_MODEL + u) * 3 + g) * B_SZ + b0 + ty * 8;
            *(float4*)dst = make_float4(col[0], col[1], col[2], col[3]);
            *(float4*)(dst + 4) = make_float4(col[4], col[5], col[6], col[7]);
        }
    }
}

// ============================================================
// Kernel 2: PERSISTENT GRU — all 96 steps, no k-split, no reduction.
// grid = 128 = 16 unit-groups(23 units -> 72 rows padded) x 8 batch-groups(32)
// 128 threads: warp w owns rows [18w, 18w+18) (= units 6w..6w+5); lane = batch.
// Wh stored TRANSPOSED: whT[k][row] (stride 74) -> row-pairs load as LDS.64,
// h dup'd once per k: 9 FFMA2 + 9 LDS.64 + 1 LDS + 1 MOV per k.
// Full dot product per thread => epilogue is pure register math.
// smem: whT[368][74] + h_s[368][36] + xpf[69][32]
// ============================================================
#define WST2 74
#define HST 36
#define WHT_FLOATS (D_MODEL * WST2)
#define HSM_FLOATS (D_MODEL * HST)
#define XPF_FLOATS (69 * 32)
#define GRU_SMEM ((WHT_FLOATS + HSM_FLOATS + XPF_FLOATS) * 4)

__global__ __launch_bounds__(128, 1)
void gru_persistent_kernel(const float* __restrict__ Wh,
                           const float* __restrict__ bh)
{
    extern __shared__ float sm[];
    float* whT = sm;                            // [368][74]
    float* h_s = sm + WHT_FLOATS;               // [368][36]
    float* xpf = sm + WHT_FLOATS + HSM_FLOATS;  // [69][32]

    const int tid = threadIdx.x;
    const int ug  = blockIdx.x >> 3;       // 0..15
    const int bgi = blockIdx.x & 7;        // 0..7
    const int b0 = bgi * 32;
    const int u_base = ug * 23;

    const int wid = tid >> 5;              // 0..3
    const int lane = tid & 31;             // batch lane

    // ---- stage Wh slice ONCE, transposed: whT[k][r], r = ul*3+g (pad r>=69 zero)
    for (int idx = tid; idx < 72 * 92; idx += 128) {
        int r = idx / 92, q = idx - r * 92;
        int ul = r / 3, g = r - ul * 3;
        float4 v = make_float4(0.f, 0.f, 0.f, 0.f);
        if (ul < 23)
            v = *(const float4*)(Wh + ((size_t)(g * D_MODEL + u_base + ul)) * D_MODEL + q * 4);
        whT[(4 * q + 0) * WST2 + r] = v.x;
        whT[(4 * q + 1) * WST2 + r] = v.y;
        whT[(4 * q + 2) * WST2 + r] = v.z;
        whT[(4 * q + 3) * WST2 + r] = v.w;
    }

    // ---- cache biases for this thread's 6 units (fixed all steps) ----
    float bhr_c[6], bhz_c[6], bhn_c[6];
#pragma unroll
    for (int j = 0; j < 6; j++) {
        int ul = 6 * wid + j;
        if (ul < 23) {
            int d = u_base + ul;
            bhr_c[j] = bh[d];
            bhz_c[j] = bh[D_MODEL + d];
            bhn_c[j] = bh[2 * D_MODEL + d];
        } else { bhr_c[j] = 0.f; bhz_c[j] = 0.f; bhn_c[j] = 0.f; }
    }

    for (int t = 0; t < T_SZ; t++) {
        const float* xT = g_xprojT + (size_t)t * D_MODEL * 3 * B_SZ;

        // ---- group A: h_{t-1} fill via cp.async ----
        if (t > 0) {
            const float* hp = g_h + (size_t)(t - 1) * D_MODEL * B_SZ;
            for (int idx = tid; idx < D_MODEL * 8; idx += 128) {
                int u = idx >> 3, c = idx & 7;
                cp16(h_s + u * HST + c * 4, hp + (size_t)u * B_SZ + b0 + c * 4);
            }
        }
        cp_commit();
        // ---- group B: xT slice prefetch (consumed in epilogue) ----
        for (int idx = tid; idx < 69 * 8; idx += 128) {
            int row = idx >> 3, c = idx & 7;     // row = ul*3+g
            int ul = row / 3, g = row - ul * 3;
            cp16(xpf + row * 32 + c * 4,
                 xT + ((size_t)(u_base + ul) * 3 + g) * B_SZ + b0 + c * 4);
        }
        cp_commit();

        cp_wait<1>();          // h_s ready (group A done)
        __syncthreads();

        // ---- full-K GEMM: 18 rows (9 row-pairs) x 1 batch per thread ----
        unsigned long long acc2[9];
#pragma unroll
        for (int p = 0; p < 9; p++) acc2[p] = 0ull;

        if (t > 0) {
            const float* wbase = whT + 18 * wid;
            const float* hcol = h_s + lane;
#pragma unroll 4
            for (int k = 0; k < D_MODEL; k++) {
                unsigned long long hd = dup_f32(hcol[k * HST]);
                const float* wk = wbase + k * WST2;
#pragma unroll
                for (int p = 0; p < 9; p++) {
                    unsigned long long w2 = *(const unsigned long long*)(wk + 2 * p);
                    fma2(acc2[p], w2, hd);
                }
            }
        }

        cp_wait<0>();          // xpf ready (long since)
        __syncthreads();

        // ---- register epilogue: 6 units x 1 batch per thread ----
        float racc[18];
#pragma unroll
        for (int p = 0; p < 9; p++) {
            float2 pr = unpack2(acc2[p]);
            racc[2 * p] = pr.x;
            racc[2 * p + 1] = pr.y;
        }

        float* hout = g_h + (size_t)t * D_MODEL * B_SZ;
#pragma unroll
        for (int j = 0; j < 6; j++) {
            int ul = 6 * wid + j;
            if (ul < 23) {
                int d = u_base + ul;
                int row0 = ul * 3 - 18 * wid;   // local row offset 3j
                float gir = xpf[(ul * 3 + 0) * 32 + lane];
                float giz = xpf[(ul * 3 + 1) * 32 + lane];
                float gin = xpf[(ul * 3 + 2) * 32 + lane];
                float rr = fast_sigmoid(gir + racc[row0 + 0] + bhr_c[j]);
                float zz = fast_sigmoid(giz + racc[row0 + 1] + bhz_c[j]);
                float nn = fast_tanh(gin + rr * (racc[row0 + 2] + bhn_c[j]));
                float hprev = (t > 0) ? h_s[d * HST + lane] : 0.f;
                hout[(size_t)d * B_SZ + b0 + lane] = (1.f - zz) * nn + zz * hprev;
            }
        }

        // ---- per-batch-group barrier (16 arrivals) ----
        __syncthreads();
        if (t < T_SZ - 1) {
            if (tid == 0) {
                __threadfence();                 // release: publish h[t]
                atomicAdd(&g_bars[bgi], 1u);
                unsigned target = 16u * (unsigned)(t + 1);
                while (*(volatile unsigned*)&g_bars[bgi] < target) { }
                __threadfence();                 // acquire
            }
            __syncthreads();
        }
    }
}

// ============================================================
// Kernel 3: heads — grid 96 (t), 256 threads (thread = batch).
// W stored transposed WT[k][32] (o=31 zero pad); per k:
// 1 coalesced LDG (h) + dup + 8 broadcast LDS.128 + 16 FFMA2.
// ============================================================
#define WTST 36
#define HEAD_SMEM ((D_MODEL * WTST + 32) * 4)

__global__ __launch_bounds__(256, 1)
void head_kernel(const float* __restrict__ Wc,
                 const float* __restrict__ bc,
                 const float* __restrict__ Wf,
                 const float* __restrict__ bf)
{
    extern __shared__ float sm[];
    float* WT     = sm;                    // [368][36] (cols 0..31 used)
    float* bias_s = sm + D_MODEL * WTST;   // [32]

    const int t  = blockIdx.x;
    const int tid = threadIdx.x;

    // zero pad column 31 (and stage real weights transposed)
    for (int k = tid; k < D_MODEL; k += 256) WT[k * WTST + 31] = 0.f;
    for (int idx = tid; idx < 31 * 92; idx += 256) {
        int o = idx / 92, q = idx - o * 92;
        const float* src = (o < 2) ? (Wc + (size_t)o * D_MODEL)
                                   : (Wf + (size_t)(o - 2) * D_MODEL);
        float4 v = *(const float4*)(src + q * 4);
        WT[(4 * q + 0) * WTST + o] = v.x;
        WT[(4 * q + 1) * WTST + o] = v.y;
        WT[(4 * q + 2) * WTST + o] = v.z;
        WT[(4 * q + 3) * WTST + o] = v.w;
    }
    if (tid < NOUT) bias_s[tid] = (tid < 2) ? bc[tid] : bf[tid - 2];
    __syncthreads();

    unsigned long long acc2[16];
#pragma unroll
    for (int p = 0; p < 16; p++) acc2[p] = 0ull;

    const float* hb = g_h + (size_t)t * D_MODEL * B_SZ + tid;
#pragma unroll 4
    for (int k = 0; k < D_MODEL; k++) {
        unsigned long long hd = dup_f32(__ldg(hb + (size_t)k * B_SZ));
        const float* wk = WT + k * WTST;
#pragma unroll
        for (int j = 0; j < 4; j++) {
            ulonglong2 w4 = *(const ulonglong2*)(wk + 8 * j);
            fma2(acc2[4 * j + 0], w4.x, hd);
            fma2(acc2[4 * j + 1], w4.y, hd);
        }
#pragma unroll
        for (int j = 0; j < 4; j++) {
            ulonglong2 w4 = *(const ulonglong2*)(wk + 8 * j + 4);
            fma2(acc2[4 * j + 2], w4.x, hd);
            fma2(acc2[4 * j + 3], w4.y, hd);
        }
    }

    // unpack: acc2 layout -> o = 8j + {0,1} (p=4j), {4,5} (p=4j+1), {2,3} (4j+2), {6,7} (4j+3)
    float res[32];
#pragma unroll
    for (int j = 0; j < 4; j++) {
        float2 a = unpack2(acc2[4 * j + 0]);
        float2 b = unpack2(acc2[4 * j + 1]);
        float2 c = unpack2(acc2[4 * j + 2]);
        float2 d = unpack2(acc2[4 * j + 3]);
        res[8 * j + 0] = a.x; res[8 * j + 1] = a.y;
        res[8 * j + 2] = b.x; res[8 * j + 3] = b.y;
        res[8 * j + 4] = c.x; res[8 * j + 5] = c.y;
        res[8 * j + 6] = d.x; res[8 * j + 7] = d.y;
    }

    float* dst = g_logitsT + ((size_t)t * B_SZ + tid) * NOUT;
#pragma unroll
    for (int o = 0; o < NOUT; o++)
        dst[o] = res[o] + bias_s[o];
}

// ============================================================
// Kernel 4: softmax + sigmoid + NMS + argmax
// ============================================================
__global__ void finalize_kernel(float* __restrict__ out)
{
    __shared__ float bg_s[T_SZ];
    const int b = blockIdx.x;
    const int t = threadIdx.x;
    const size_t mi = (size_t)b * T_SZ + t;
    const float* L = g_logitsT + ((size_t)t * B_SZ + b) * NOUT;

    float l0 = L[0], l1 = L[1];
    float mx = fmaxf(l0, l1);
    float e0 = expf(l0 - mx), e1 = expf(l1 - mx);
    float inv = 1.f / (e0 + e1);
    float s0 = e0 * inv, s1 = e1 * inv;
    bg_s[t] = s0;

#pragma unroll
    for (int j = 0; j < NCLS; j++) {
        float v = 1.f / (1.f + expf(-L[2 + j]));
        out[(size_t)M_ROWS * 3 + mi * NCLS + j] = v;
    }
    __syncthreads();

    float wmin = s0;
#pragma unroll
    for (int dt = -2; dt <= 2; dt++) {
        int tt = t + dt;
        if (tt >= 0 && tt < T_SZ) wmin = fminf(wmin, bg_s[tt]);
    }
    bool keep = (s0 == wmin);
    float n0 = keep ? s0 : 0.f;
    float n1 = keep ? s1 : 0.f;

    out[mi] = (n1 > n0) ? 1.f : 0.f;
    out[M_ROWS + mi * 2 + 0] = n0;
    out[M_ROWS + mi * 2 + 1] = n1;
}

// ============================================================
extern "C" void kernel_launch(void* const* d_in, const int* in_sizes, int n_in,
                              void* d_out, int out_size)
{
    const float* features = (const float*)d_in[0];
    // d_in[1] = hand (unused)
    const float* Wi = (const float*)d_in[2];
    const float* Wh = (const float*)d_in[3];
    const float* bi = (const float*)d_in[4];
    const float* bh = (const float*)d_in[5];
    const float* Wc = (const float*)d_in[6];
    const float* bc = (const float*)d_in[7];
    const float* Wf = (const float*)d_in[8];
    const float* bf = (const float*)d_in[9];
    float* out = (float*)d_out;

    cudaFuncSetAttribute(gru_persistent_kernel,
                         cudaFuncAttributeMaxDynamicSharedMemorySize, GRU_SMEM);
    cudaFuncSetAttribute(head_kernel,
                         cudaFuncAttributeMaxDynamicSharedMemorySize, HEAD_SMEM);

    // 0) reset barriers
    init_bar_kernel<<<1, 1>>>();

    // 1) input projection, writing [t][u][g][b] directly
    xproj_kernel<<<dim3(18, 2, T_SZ), 256>>>(features, Wi, bi);

    // 2) recurrence: ONE persistent launch for all 96 steps
    gru_persistent_kernel<<<128, 128, GRU_SMEM>>>(Wh, bh);

    // 3) output heads (transposed weights, FFMA2)
    head_kernel<<<T_SZ, 256, HEAD_SMEM>>>(Wc, bc, Wf, bf);

    // 4) softmax/sigmoid/NMS/argmax
    finalize_kernel<<<B_SZ, T_SZ>>>(out);
}

// round 14
// speedup vs baseline: 1.9620x; 1.9620x over previous
#include <cuda_runtime.h>
#include <math.h>

// Problem constants
#define B_SZ 256
#define T_SZ 96
#define F_DIM 368
#define D_MODEL 368
#define G3 1104          // 3*D_MODEL
#define NCLS 29
#define NOUT 31          // 2 coarse + 29 fine
#define M_ROWS 24576     // B*T

// -------- device scratch --------
__device__ float g_xprojT[(size_t)T_SZ * D_MODEL * 3 * B_SZ];  // [t][u][g][b]
__device__ float g_h[(size_t)T_SZ * D_MODEL * B_SZ];           // [t][d][b]
__device__ float g_logitsT[(size_t)T_SZ * B_SZ * NOUT];        // [t][b][o]
__device__ unsigned g_bars[8];                                 // per-batch-group barriers

// -------- packed f32x2 helpers (Blackwell FFMA2) --------
__device__ __forceinline__ unsigned long long dup_f32(float f) {
    unsigned long long r;
    asm("mov.b64 %0, {%1, %1};" : "=l"(r) : "r"(__float_as_uint(f)));
    return r;
}
__device__ __forceinline__ unsigned long long pack_f32(float lo, float hi) {
    unsigned long long r;
    asm("mov.b64 %0, {%1, %2};" : "=l"(r) : "r"(__float_as_uint(lo)), "r"(__float_as_uint(hi)));
    return r;
}
__device__ __forceinline__ void fma2(unsigned long long& d,
                                     unsigned long long a, unsigned long long b) {
    asm("fma.rn.f32x2 %0, %1, %2, %0;" : "+l"(d) : "l"(a), "l"(b));
}
__device__ __forceinline__ float2 unpack2(unsigned long long v) {
    unsigned lo, hi;
    asm("mov.b64 {%0, %1}, %2;" : "=r"(lo), "=r"(hi) : "l"(v));
    return make_float2(__uint_as_float(lo), __uint_as_float(hi));
}
__device__ __forceinline__ float fast_sigmoid(float x) {
    return __fdividef(1.f, 1.f + expf(-x));
}
__device__ __forceinline__ float fast_tanh(float x) {
    return __fdividef(2.f, 1.f + expf(-2.f * x)) - 1.f;
}

// -------- cp.async helpers --------
__device__ __forceinline__ void cp16(void* smem_dst, const void* gsrc) {
    unsigned d = (unsigned)__cvta_generic_to_shared(smem_dst);
    asm volatile("cp.async.cg.shared.global [%0], [%1], 16;\n" :: "r"(d), "l"(gsrc));
}
__device__ __forceinline__ void cp_commit() {
    asm volatile("cp.async.commit_group;\n");
}
template <int N>
__device__ __forceinline__ void cp_wait() {
    asm volatile("cp.async.wait_group %0;\n" :: "n"(N));
}

// ============================================================
// init kernel: reset barriers (runs each graph replay)
// ============================================================
__global__ void init_bar_kernel() {
    for (int i = 0; i < 8; i++) g_bars[i] = 0u;
}

// ============================================================
// Kernel 1: xproj direct into [t][u][g][b] layout.
// grid (18 n-tiles, 2 b-tiles, 96 t), 256 threads, BK=16, tile 8b x 4n
// ============================================================
__global__ void xproj_kernel(const float* __restrict__ A,
                             const float* __restrict__ W,
                             const float* __restrict__ bi)
{
    __shared__ float As[16][128];
    __shared__ float Bs[16][64];

    const int t  = blockIdx.z;
    const int b0 = blockIdx.y * 128;
    const int n0 = blockIdx.x * 64;
    const int tid = threadIdx.x;
    const int tx = tid & 15;        // 4 n each
    const int ty = tid >> 4;        // 8 b each

    unsigned long long accp[8][2];
#pragma unroll
    for (int i = 0; i < 8; i++) { accp[i][0] = 0ull; accp[i][1] = 0ull; }

    for (int k0 = 0; k0 < F_DIM; k0 += 16) {
#pragma unroll
        for (int l = 0; l < 2; l++) {
            int idx = tid + l * 256;
            int row = idx >> 2, kq = idx & 3;   // row = batch lane
            float4 v = *(const float4*)(A + ((size_t)(b0 + row) * T_SZ + t) * F_DIM + k0 + kq * 4);
            As[kq * 4 + 0][row] = v.x;
            As[kq * 4 + 1][row] = v.y;
            As[kq * 4 + 2][row] = v.z;
            As[kq * 4 + 3][row] = v.w;
        }
        {
            int row = tid >> 2, kq = tid & 3;
            int n = n0 + row;
            float4 v = make_float4(0.f, 0.f, 0.f, 0.f);
            if (n < G3)
                v = *(const float4*)(W + (size_t)n * F_DIM + k0 + kq * 4);
            Bs[kq * 4 + 0][row] = v.x;
            Bs[kq * 4 + 1][row] = v.y;
            Bs[kq * 4 + 2][row] = v.z;
            Bs[kq * 4 + 3][row] = v.w;
        }
        __syncthreads();
#pragma unroll
        for (int k = 0; k < 16; k++) {
            ulonglong2 bq = *(const ulonglong2*)&Bs[k][tx * 4];
#pragma unroll
            for (int i = 0; i < 8; i++) {
                unsigned long long ap = dup_f32(As[k][ty * 8 + i]);
                fma2(accp[i][0], ap, bq.x);
                fma2(accp[i][1], ap, bq.y);
            }
        }
        __syncthreads();
    }

    // write transposed: for each n, 8 consecutive batches
#pragma unroll
    for (int j = 0; j < 4; j++) {
        int n = n0 + tx * 4 + j;
        if (n < G3) {
            int g = n / D_MODEL, u = n - g * D_MODEL;
            float bv = bi[n];
            float col[8];
#pragma unroll
            for (int i = 0; i < 8; i++) {
                float2 p = unpack2(accp[i][j >> 1]);
                col[i] = ((j & 1) ? p.y : p.x) + bv;
            }
            float* dst = g_xprojT + (((size_t)t * D_MODEL + u) * 3 + g) * B_SZ + b0 + ty * 8;
            *(float4*)dst = make_float4(col[0], col[1], col[2], col[3]);
            *(float4*)(dst + 4) = make_float4(col[4], col[5], col[6], col[7]);
        }
    }
}

// ============================================================
// Kernel 2: PERSISTENT GRU — all 96 steps in one launch (R11 config).
// grid = 128 = 16 unit-groups(23 units = 69 rows, pad 72) x 8 batch-groups(32)
// 128 threads: tid = kq*32 + rg*4 + bg  (warp = kq; 1 warp/SMSP)
// thread tile: 9 rows x 8 batches -> 36 FFMA2 per k.
// h-fill + xT prefetch via cp.async; per-batch-group barrier (16 arrivals).
// smem: wh_s[72][388] + h_s[368][36] + red_s[4][72*36] + xpf[69*32]
// ============================================================
#define WST 388
#define HST 36
#define WH_FLOATS (72 * WST)
#define HSM_FLOATS (D_MODEL * HST)
#define RED_STRIDE (72 * 36)
#define RED_FLOATS (4 * RED_STRIDE)
#define XPF_FLOATS (69 * 32)
#define GRU_SMEM ((WH_FLOATS + HSM_FLOATS + RED_FLOATS + XPF_FLOATS) * 4)

__global__ __launch_bounds__(128, 1)
void gru_persistent_kernel(const float* __restrict__ Wh,
                           const float* __restrict__ bh)
{
    extern __shared__ float sm[];
    float* wh_s  = sm;                                        // [72][388]
    float* h_s   = sm + WH_FLOATS;                            // [368][36]
    float* red_s = sm + WH_FLOATS + HSM_FLOATS;               // [4][72*36]
    float* xpf   = sm + WH_FLOATS + HSM_FLOATS + RED_FLOATS;  // [69][32]

    const int tid = threadIdx.x;
    const int ug  = blockIdx.x >> 3;       // 0..15
    const int bgi = blockIdx.x & 7;        // 0..7
    const int b0 = bgi * 32;
    const int u_base = ug * 23;

    const int kq = tid >> 5;               // 0..3 (warp id)
    const int lane = tid & 31;
    const int rg = lane >> 2;              // 0..7
    const int bg = lane & 3;               // 0..3

    // ---- stage Wh slice ONCE: rows r = ul*3+g (ul 0..22 real, 23 pad) ----
    for (int idx = tid; idx < 72 * 92; idx += 128) {
        int r = idx / 92, q = idx - r * 92;
        int ul = r / 3, g = r - ul * 3;
        float4 v = make_float4(0.f, 0.f, 0.f, 0.f);
        if (ul < 23)
            v = *(const float4*)(Wh + ((size_t)(g * D_MODEL + u_base + ul)) * D_MODEL + q * 4);
        *(float4*)(wh_s + r * WST + q * 4) = v;
    }

    // ---- cache biases for this thread's 6 epilogue outputs (fixed all steps) ----
    float bhr_c[6], bhz_c[6], bhn_c[6];
#pragma unroll
    for (int i = 0; i < 6; i++) {
        int o = tid + i * 128;
        int ul = o >> 5;
        if (ul < 23) {
            int d = u_base + ul;
            bhr_c[i] = bh[d];
            bhz_c[i] = bh[D_MODEL + d];
            bhn_c[i] = bh[2 * D_MODEL + d];
        } else { bhr_c[i] = 0.f; bhz_c[i] = 0.f; bhn_c[i] = 0.f; }
    }

    for (int t = 0; t < T_SZ; t++) {
        const float* xT = g_xprojT + (size_t)t * D_MODEL * 3 * B_SZ;

        // ---- group A: h_{t-1} fill via cp.async ----
        if (t > 0) {
            const float* hp = g_h + (size_t)(t - 1) * D_MODEL * B_SZ;
            for (int idx = tid; idx < D_MODEL * 8; idx += 128) {
                int u = idx >> 3, c = idx & 7;
                cp16(h_s + u * HST + c * 4, hp + (size_t)u * B_SZ + b0 + c * 4);
            }
        }
        cp_commit();
        // ---- group B: xT slice prefetch (consumed in epilogue) ----
        for (int idx = tid; idx < 69 * 8; idx += 128) {
            int row = idx >> 3, c = idx & 7;     // row = ul*3+g
            int ul = row / 3, g = row - ul * 3;
            cp16(xpf + row * 32 + c * 4,
                 xT + ((size_t)(u_base + ul) * 3 + g) * B_SZ + b0 + c * 4);
        }
        cp_commit();

        cp_wait<1>();          // h_s ready (group A done)
        __syncthreads();

        // ---- partial GEMM: 9 rows x 8 batches (4 f32x2 pairs) ----
        unsigned long long acc2[9][4];
#pragma unroll
        for (int j = 0; j < 9; j++)
#pragma unroll
            for (int p = 0; p < 4; p++) acc2[j][p] = 0ull;

        if (t > 0) {
            const float* wp = wh_s + (rg * 9) * WST + kq * 92;
            const float* hp2 = h_s + (kq * 92) * HST + bg * 8;
#pragma unroll 4
            for (int k = 0; k < 92; k++) {
                ulonglong2 hv0 = *(const ulonglong2*)(hp2 + k * HST);
                ulonglong2 hv1 = *(const ulonglong2*)(hp2 + k * HST + 4);
#pragma unroll
                for (int j = 0; j < 9; j++) {
                    unsigned long long wd = dup_f32(wp[j * WST + k]);
                    fma2(acc2[j][0], hv0.x, wd);
                    fma2(acc2[j][1], hv0.y, wd);
                    fma2(acc2[j][2], hv1.x, wd);
                    fma2(acc2[j][3], hv1.y, wd);
                }
            }
        }
        __syncthreads();

        // ---- write partials ----
        {
            float* dst = red_s + kq * RED_STRIDE;
#pragma unroll
            for (int j = 0; j < 9; j++) {
                int row = rg * 9 + j;
                *(ulonglong2*)(dst + row * 36 + bg * 8) =
                    make_ulonglong2(acc2[j][0], acc2[j][1]);
                *(ulonglong2*)(dst + row * 36 + bg * 8 + 4) =
                    make_ulonglong2(acc2[j][2], acc2[j][3]);
            }
        }
        cp_wait<0>();          // xpf ready (long since)
        __syncthreads();

        // ---- parallel epilogue: each thread 6 outputs (unit, batch) ----
        float* hout = g_h + (size_t)t * D_MODEL * B_SZ;
#pragma unroll
        for (int i = 0; i < 6; i++) {
            int o = tid + i * 128;        // 0..767
            int ul = o >> 5;              // 0..23 (23 = pad)
            int b  = o & 31;
            if (ul < 23) {
                int d = u_base + ul;
                int row0 = ul * 3;
                float gsum[3];
#pragma unroll
                for (int g = 0; g < 3; g++) {
                    int row = row0 + g;
                    gsum[g] = red_s[0 * RED_STRIDE + row * 36 + b]
                            + red_s[1 * RED_STRIDE + row * 36 + b]
                            + red_s[2 * RED_STRIDE + row * 36 + b]
                            + red_s[3 * RED_STRIDE + row * 36 + b];
                }
                float gir = xpf[(row0 + 0) * 32 + b];
                float giz = xpf[(row0 + 1) * 32 + b];
                float gin = xpf[(row0 + 2) * 32 + b];
                float rr = fast_sigmoid(gir + gsum[0] + bhr_c[i]);
                float zz = fast_sigmoid(giz + gsum[1] + bhz_c[i]);
                float nn = fast_tanh(gin + rr * (gsum[2] + bhn_c[i]));
                float hprev = (t > 0) ? h_s[d * HST + b] : 0.f;
                hout[(size_t)d * B_SZ + b0 + b] = (1.f - zz) * nn + zz * hprev;
            }
        }

        // ---- per-batch-group barrier (16 arrivals) ----
        __syncthreads();
        if (t < T_SZ - 1) {
            if (tid == 0) {
                __threadfence();                 // release: publish h[t]
                atomicAdd(&g_bars[bgi], 1u);
                unsigned target = 16u * (unsigned)(t + 1);
                while (*(volatile unsigned*)&g_bars[bgi] < target) { }
                __threadfence();                 // acquire
            }
            __syncthreads();
        }
    }
}

// ============================================================
// Kernel 3: heads per-t from g_h: logitsT[t][b][o]
// grid (96, 2), 128 threads (thread = one batch), K chunks of 92.
// PAIR-OVER-K: acc2[o] += (w_k,w_{k+1}) (x) (h_k,h_{k+1})  [FFMA2]
// W_s stays k-contiguous -> weight pairs load as one broadcast LDS.64.
// smem: W_s[31][368] + bias_s[32] + A_s[92][128]  (R11 layout)
// ============================================================
#define HEAD_SMEM ((31 * 368 + 32 + 92 * 128) * 4)

__global__ __launch_bounds__(128, 1)
void head_kernel(const float* __restrict__ Wc,
                 const float* __restrict__ bc,
                 const float* __restrict__ Wf,
                 const float* __restrict__ bf)
{
    extern __shared__ float sm[];
    float* W_s    = sm;                  // [31][368]
    float* bias_s = sm + 31 * 368;       // [32]
    float* A_s    = bias_s + 32;         // [92][128]

    const int t  = blockIdx.x;
    const int b0 = blockIdx.y * 128;
    const int tid = threadIdx.x;

    for (int idx = tid; idx < 31 * 92; idx += 128) {
        int row = idx / 92, kq = idx % 92;
        const float* src = (row < 2) ? (Wc + (size_t)row * D_MODEL)
                                     : (Wf + (size_t)(row - 2) * D_MODEL);
        float4 v = *(const float4*)(src + kq * 4);
        *(float4*)(W_s + row * D_MODEL + kq * 4) = v;
    }
    if (tid < NOUT) bias_s[tid] = (tid < 2) ? bc[tid] : bf[tid - 2];

    unsigned long long acc2[NOUT];
#pragma unroll
    for (int o = 0; o < NOUT; o++) acc2[o] = 0ull;

    for (int c = 0; c < 4; c++) {
        __syncthreads();
        for (int idx = tid; idx < 92 * 32; idx += 128) {
            int r = idx >> 5, cc = idx & 31;
            float4 v = *(const float4*)(g_h +
                         ((size_t)t * D_MODEL + c * 92 + r) * B_SZ + b0 + cc * 4);
            *(float4*)(A_s + r * 128 + cc * 4) = v;
        }
        __syncthreads();
#pragma unroll 2
        for (int kp = 0; kp < 46; kp++) {
            float h0 = A_s[(2 * kp) * 128 + tid];
            float h1 = A_s[(2 * kp + 1) * 128 + tid];
            unsigned long long hp = pack_f32(h0, h1);
            const float* wk = W_s + c * 92 + 2 * kp;
#pragma unroll
            for (int o = 0; o < NOUT; o++) {
                unsigned long long w2 = *(const unsigned long long*)(wk + o * D_MODEL);
                fma2(acc2[o], w2, hp);
            }
        }
    }

    float* dst = g_logitsT + ((size_t)t * B_SZ + b0 + tid) * NOUT;
#pragma unroll
    for (int o = 0; o < NOUT; o++) {
        float2 p = unpack2(acc2[o]);
        dst[o] = p.x + p.y + bias_s[o];
    }
}

// ============================================================
// Kernel 4: softmax + sigmoid + NMS + argmax
// block per batch (256), thread per t (96); logits from logitsT[t][b][o]
// ============================================================
__global__ void finalize_kernel(float* __restrict__ out)
{
    __shared__ float bg_s[T_SZ];
    const int b = blockIdx.x;
    const int t = threadIdx.x;
    const size_t mi = (size_t)b * T_SZ + t;
    const float* L = g_logitsT + ((size_t)t * B_SZ + b) * NOUT;

    float l0 = L[0], l1 = L[1];
    float mx = fmaxf(l0, l1);
    float e0 = expf(l0 - mx), e1 = expf(l1 - mx);
    float inv = 1.f / (e0 + e1);
    float s0 = e0 * inv, s1 = e1 * inv;
    bg_s[t] = s0;

#pragma unroll
    for (int j = 0; j < NCLS; j++) {
        float v = 1.f / (1.f + expf(-L[2 + j]));
        out[(size_t)M_ROWS * 3 + mi * NCLS + j] = v;
    }
    __syncthreads();

    float wmin = s0;
#pragma unroll
    for (int dt = -2; dt <= 2; dt++) {
        int tt = t + dt;
        if (tt >= 0 && tt < T_SZ) wmin = fminf(wmin, bg_s[tt]);
    }
    bool keep = (s0 == wmin);
    float n0 = keep ? s0 : 0.f;
    float n1 = keep ? s1 : 0.f;

    out[mi] = (n1 > n0) ? 1.f : 0.f;
    out[M_ROWS + mi * 2 + 0] = n0;
    out[M_ROWS + mi * 2 + 1] = n1;
}

// ============================================================
extern "C" void kernel_launch(void* const* d_in, const int* in_sizes, int n_in,
                              void* d_out, int out_size)
{
    const float* features = (const float*)d_in[0];
    // d_in[1] = hand (unused)
    const float* Wi = (const float*)d_in[2];
    const float* Wh = (const float*)d_in[3];
    const float* bi = (const float*)d_in[4];
    const float* bh = (const float*)d_in[5];
    const float* Wc = (const float*)d_in[6];
    const float* bc = (const float*)d_in[7];
    const float* Wf = (const float*)d_in[8];
    const float* bf = (const float*)d_in[9];
    float* out = (float*)d_out;

    cudaFuncSetAttribute(gru_persistent_kernel,
                         cudaFuncAttributeMaxDynamicSharedMemorySize, GRU_SMEM);
    cudaFuncSetAttribute(head_kernel,
                         cudaFuncAttributeMaxDynamicSharedMemorySize, HEAD_SMEM);

    // 0) reset barriers
    init_bar_kernel<<<1, 1>>>();

    // 1) input projection, writing [t][u][g][b] directly
    xproj_kernel<<<dim3(18, 2, T_SZ), 256>>>(features, Wi, bi);

    // 2) recurrence: ONE persistent launch for all 96 steps
    gru_persistent_kernel<<<128, 128, GRU_SMEM>>>(Wh, bh);

    // 3) output heads (pair-over-k FFMA2)
    head_kernel<<<dim3(T_SZ, 2), 128, HEAD_SMEM>>>(Wc, bc, Wf, bf);

    // 4) softmax/sigmoid/NMS/argmax
    finalize_kernel<<<B_SZ, T_SZ>>>(out);
}